// round 1
// baseline (speedup 1.0000x reference)
#include <cuda_runtime.h>
#include <math_constants.h>

// DarkChannel: img [16,3,1024,1024] f32 -> channel-min -> 15x15 min-filter (erosion,
// +inf border) -> out [16,1,1024,1024] f32.
//
// Two memory-bound passes:
//   k_vert: channel-min fused with vertical 15-window min (van Herk, block==window==15)
//   k_horz: horizontal 15-window min with overlapping vectorized loads
//
// Scratch: __device__ global (no allocations allowed in kernel_launch).

#define IMG_H 1024
#define IMG_W 1024
#define IMG_B 16
#define CH_STRIDE (IMG_H * IMG_W)

__device__ float g_tmp[IMG_B * IMG_H * IMG_W];

__device__ __forceinline__ float4 min4(float4 a, float4 b) {
    return make_float4(fminf(a.x, b.x), fminf(a.y, b.y),
                       fminf(a.z, b.z), fminf(a.w, b.w));
}

__device__ __forceinline__ float4 cmin_load(const float* p, int y) {
    // channel-min of 3 channels at row y, or +inf if y out of range
    if ((unsigned)y >= (unsigned)IMG_H) {
        return make_float4(CUDART_INF_F, CUDART_INF_F, CUDART_INF_F, CUDART_INF_F);
    }
    const float* r = p + (size_t)y * IMG_W;
    float4 c0 = *reinterpret_cast<const float4*>(r);
    float4 c1 = *reinterpret_cast<const float4*>(r + CH_STRIDE);
    float4 c2 = *reinterpret_cast<const float4*>(r + 2 * CH_STRIDE);
    return min4(min4(c0, c1), c2);
}

// Vertical pass: each thread owns 4 consecutive x (float4) and a tile of 15 output
// rows. van Herk with block size == window size == 15:
//   out[y0]     = suffix-min over input t in [0,14]           (h[0])
//   out[y0+r]   = min(h[r], prefix-min of next block up to r) (r = 1..14)
__global__ __launch_bounds__(256) void k_vert(const float* __restrict__ img) {
    const int x  = threadIdx.x << 2;          // blockDim.x == 256 -> covers full width
    const int b  = blockIdx.z;
    const int y0 = blockIdx.y * 15;

    const float* p = img + (size_t)b * 3 * CH_STRIDE + x;

    float4 h[15];
#pragma unroll
    for (int t = 0; t < 15; ++t) {
        h[t] = cmin_load(p, y0 - 7 + t);      // input rows y0-7 .. y0+7
    }
    // suffix mins within the block
#pragma unroll
    for (int t = 13; t >= 0; --t) {
        h[t] = min4(h[t], h[t + 1]);
    }

    float* outp = g_tmp + ((size_t)b * IMG_H) * IMG_W + x;
    // y0 <= 68*15 = 1020 < 1024 always valid
    *reinterpret_cast<float4*>(outp + (size_t)y0 * IMG_W) = h[0];

    float4 g = make_float4(CUDART_INF_F, CUDART_INF_F, CUDART_INF_F, CUDART_INF_F);
#pragma unroll
    for (int r = 1; r < 15; ++r) {
        float4 v = cmin_load(p, y0 + 7 + r);  // input row t = 14 + r (next block)
        g = min4(g, v);
        if (y0 + r < IMG_H) {
            *reinterpret_cast<float4*>(outp + (size_t)(y0 + r) * IMG_W) = min4(h[r], g);
        }
    }
}

// Horizontal pass: each thread produces an aligned float4 of outputs at x0 = 4*tid.
// Windows for outputs j=0..3 cover local floats f[k], k = (x - x0 + 8) in [j+1, j+15].
// Load 5 overlapping float4 (f[0..19]); shared core = min(f[4..15]).
__global__ __launch_bounds__(256) void k_horz(float* __restrict__ out) {
    const int x0 = threadIdx.x << 2;          // blockDim.x == 256 -> covers full width
    const int y  = blockIdx.y;
    const int b  = blockIdx.z;

    const float* row = g_tmp + ((size_t)b * IMG_H + y) * IMG_W;

    float f[20];
    const float4 INF4 = make_float4(CUDART_INF_F, CUDART_INF_F, CUDART_INF_F, CUDART_INF_F);
#pragma unroll
    for (int q = 0; q < 5; ++q) {
        int xq = x0 - 8 + q * 4;              // float4-aligned
        float4 v = ((unsigned)xq < (unsigned)IMG_W)
                       ? *reinterpret_cast<const float4*>(row + xq)
                       : INF4;
        f[q * 4 + 0] = v.x;
        f[q * 4 + 1] = v.y;
        f[q * 4 + 2] = v.z;
        f[q * 4 + 3] = v.w;
    }

    float core = f[4];
#pragma unroll
    for (int k = 5; k <= 15; ++k) core = fminf(core, f[k]);

    float p23   = fminf(f[2], f[3]);
    float p1617 = fminf(f[16], f[17]);

    float4 o;
    o.x = fminf(core, fminf(f[1], p23));
    o.y = fminf(core, fminf(p23, f[16]));
    o.z = fminf(core, fminf(f[3], p1617));
    o.w = fminf(core, fminf(p1617, f[18]));

    float* orow = out + ((size_t)b * IMG_H + y) * IMG_W;
    *reinterpret_cast<float4*>(orow + x0) = o;
}

extern "C" void kernel_launch(void* const* d_in, const int* in_sizes, int n_in,
                              void* d_out, int out_size) {
    const float* img = (const float*)d_in[0];
    float* out = (float*)d_out;

    // vertical: 69 y-tiles of 15 rows (last tile partially masked), 16 batches
    dim3 gv(1, (IMG_H + 14) / 15, IMG_B);
    k_vert<<<gv, 256>>>(img);

    // horizontal: one block per (row, batch)
    dim3 gh(1, IMG_H, IMG_B);
    k_horz<<<gh, 256>>>(out);
}

// round 2
// speedup vs baseline: 1.2032x; 1.2032x over previous
#include <cuda_runtime.h>
#include <math_constants.h>

// DarkChannel fused single-kernel:
//   channel-min over C=3  ->  vertical 15-min (van Herk, reg)  ->  smem
//   ->  horizontal 15-min (overlapping float4 loads from smem) ->  out
//
// img [16,3,1024,1024] f32 -> out [16,1,1024,1024] f32, +inf border erosion.

#define IMG_H 1024
#define IMG_W 1024
#define IMG_B 16
#define CH_STRIDE (IMG_H * IMG_W)
#define YTILE 15

__device__ __forceinline__ float4 min4(float4 a, float4 b) {
    return make_float4(fminf(a.x, b.x), fminf(a.y, b.y),
                       fminf(a.z, b.z), fminf(a.w, b.w));
}

__device__ __forceinline__ float4 cmin_load(const float* p, int y) {
    if ((unsigned)y >= (unsigned)IMG_H) {
        return make_float4(CUDART_INF_F, CUDART_INF_F, CUDART_INF_F, CUDART_INF_F);
    }
    const float* r = p + (size_t)y * IMG_W;
    float4 c0 = *reinterpret_cast<const float4*>(r);
    float4 c1 = *reinterpret_cast<const float4*>(r + CH_STRIDE);
    float4 c2 = *reinterpret_cast<const float4*>(r + 2 * CH_STRIDE);
    return min4(min4(c0, c1), c2);
}

// One block: batch b, 15 output rows [y0, y0+15), full width.
// Phase 1: vertical van Herk (block size == window == 15) into smem.
// Phase 2: horizontal 15-window min from smem, write gmem.
extern "C" __global__ __launch_bounds__(256)
void k_fused(const float* __restrict__ img, float* __restrict__ out) {
    extern __shared__ float sV[];             // YTILE * IMG_W floats (60 KB)

    const int x  = threadIdx.x << 2;          // 256 threads cover width in float4
    const int ty = blockIdx.x;                // y-tile index 0..68
    const int b  = blockIdx.y;
    const int y0 = ty * YTILE;

    const float* p = img + (size_t)b * 3 * CH_STRIDE + x;

    // ---- Phase 1: vertical min over rows y0-7 .. y0+7+r ----
    float4 h[YTILE];
#pragma unroll
    for (int t = 0; t < YTILE; ++t) {
        h[t] = cmin_load(p, y0 - 7 + t);
    }
#pragma unroll
    for (int t = YTILE - 2; t >= 0; --t) {
        h[t] = min4(h[t], h[t + 1]);          // suffix mins
    }

    // row 0 of tile
    *reinterpret_cast<float4*>(&sV[0 * IMG_W + x]) = h[0];

    float4 g = make_float4(CUDART_INF_F, CUDART_INF_F, CUDART_INF_F, CUDART_INF_F);
#pragma unroll
    for (int r = 1; r < YTILE; ++r) {
        g = min4(g, cmin_load(p, y0 + 7 + r));    // running prefix of next block
        *reinterpret_cast<float4*>(&sV[r * IMG_W + x]) = min4(h[r], g);
    }

    __syncthreads();

    // ---- Phase 2: horizontal 15-window min from smem ----
    const int x0 = x;                          // aligned float4 of outputs
    const int vrows = min(YTILE, IMG_H - y0);  // last tile has 4 valid rows
    float* ob = out + ((size_t)b * IMG_H + y0) * IMG_W + x0;

    const float4 INF4 = make_float4(CUDART_INF_F, CUDART_INF_F, CUDART_INF_F, CUDART_INF_F);

    for (int r = 0; r < vrows; ++r) {
        const float* row = &sV[r * IMG_W];
        float f[20];
#pragma unroll
        for (int q = 0; q < 5; ++q) {
            int xq = x0 - 8 + q * 4;           // float4-aligned
            float4 v = ((unsigned)xq < (unsigned)IMG_W)
                           ? *reinterpret_cast<const float4*>(row + xq)
                           : INF4;
            f[q * 4 + 0] = v.x;
            f[q * 4 + 1] = v.y;
            f[q * 4 + 2] = v.z;
            f[q * 4 + 3] = v.w;
        }

        float core = f[4];
#pragma unroll
        for (int k = 5; k <= 15; ++k) core = fminf(core, f[k]);

        float p23   = fminf(f[2], f[3]);
        float p1617 = fminf(f[16], f[17]);

        float4 o;
        o.x = fminf(core, fminf(f[1], p23));
        o.y = fminf(core, fminf(p23, f[16]));
        o.z = fminf(core, fminf(f[3], p1617));
        o.w = fminf(core, fminf(p1617, f[18]));

        *reinterpret_cast<float4*>(ob + (size_t)r * IMG_W) = o;
    }
}

extern "C" void kernel_launch(void* const* d_in, const int* in_sizes, int n_in,
                              void* d_out, int out_size) {
    const float* img = (const float*)d_in[0];
    float* out = (float*)d_out;

    const int smem = YTILE * IMG_W * sizeof(float);   // 61440 B
    static bool attr_set = false;
    if (!attr_set) {
        cudaFuncSetAttribute(k_fused, cudaFuncAttributeMaxDynamicSharedMemorySize, smem);
        attr_set = true;
    }

    dim3 grid((IMG_H + YTILE - 1) / YTILE, IMG_B);    // 69 x 16
    k_fused<<<grid, 256, smem>>>(img, out);
}

// round 3
// speedup vs baseline: 1.2871x; 1.0697x over previous
#include <cuda_runtime.h>
#include <math_constants.h>

// DarkChannel fused: channel-min(C=3) -> vertical 15-min (van Herk, float2 regs)
// -> smem (15 rows) -> horizontal 15-min (float4 smem reads, rows split across
// two thread row-groups) -> out.  +inf border.
//
// img [16,3,1024,1024] f32 -> out [16,1,1024,1024] f32.

#define IMG_H 1024
#define IMG_W 1024
#define IMG_B 16
#define CH_STRIDE (IMG_H * IMG_W)
#define YTILE 15

__device__ __forceinline__ float2 min2(float2 a, float2 b) {
    return make_float2(fminf(a.x, b.x), fminf(a.y, b.y));
}

template <bool CHECK>
__device__ __forceinline__ float2 cmin_load2(const float* p, int y) {
    if (CHECK && (unsigned)y >= (unsigned)IMG_H) {
        return make_float2(CUDART_INF_F, CUDART_INF_F);
    }
    const float* r = p + (size_t)y * IMG_W;
    float2 c0 = *reinterpret_cast<const float2*>(r);
    float2 c1 = *reinterpret_cast<const float2*>(r + CH_STRIDE);
    float2 c2 = *reinterpret_cast<const float2*>(r + 2 * CH_STRIDE);
    return min2(min2(c0, c1), c2);
}

template <bool CHECK>
__device__ __forceinline__ void vert_pass(const float* p, float* sV, int x2, int y0) {
    float2 h[YTILE];
#pragma unroll
    for (int t = 0; t < YTILE; ++t) {
        h[t] = cmin_load2<CHECK>(p, y0 - 7 + t);   // rows y0-7 .. y0+7
    }
#pragma unroll
    for (int t = YTILE - 2; t >= 0; --t) {
        h[t] = min2(h[t], h[t + 1]);               // suffix mins
    }

    *reinterpret_cast<float2*>(&sV[0 * IMG_W + x2]) = h[0];

    float2 g = make_float2(CUDART_INF_F, CUDART_INF_F);
#pragma unroll
    for (int r = 1; r < YTILE; ++r) {
        g = min2(g, cmin_load2<CHECK>(p, y0 + 7 + r));  // next-block prefix
        *reinterpret_cast<float2*>(&sV[r * IMG_W + x2]) = min2(h[r], g);
    }
}

extern "C" __global__ __launch_bounds__(512, 2)
void k_fused(const float* __restrict__ img, float* __restrict__ out) {
    extern __shared__ float sV[];                  // YTILE * IMG_W floats (60 KB)

    const int tid = threadIdx.x;                   // 512 threads
    const int ty  = blockIdx.x;                    // y-tile 0..68
    const int b   = blockIdx.y;
    const int y0  = ty * YTILE;

    // ---- Phase 1: vertical van Herk, float2 per thread ----
    {
        const int x2 = tid << 1;                   // 512 threads * 2 floats = 1024
        const float* p = img + (size_t)b * 3 * CH_STRIDE + x2;
        if (y0 >= 7 && y0 + 21 < IMG_H) {
            vert_pass<false>(p, sV, x2, y0);       // interior: no bounds checks
        } else {
            vert_pass<true>(p, sV, x2, y0);
        }
    }

    __syncthreads();

    // ---- Phase 2: horizontal 15-min from smem; rows split across 2 groups ----
    const int tx   = tid & 255;
    const int rgrp = tid >> 8;                     // 0 or 1
    const int x0   = tx << 2;                      // aligned float4 of outputs
    const int vrows = min(YTILE, IMG_H - y0);

    const float4 INF4 = make_float4(CUDART_INF_F, CUDART_INF_F, CUDART_INF_F, CUDART_INF_F);
    float* ob = out + ((size_t)b * IMG_H + y0) * IMG_W + x0;

    for (int r = rgrp; r < vrows; r += 2) {
        const float* row = &sV[r * IMG_W];
        float f[20];
#pragma unroll
        for (int q = 0; q < 5; ++q) {
            int xq = x0 - 8 + q * 4;               // float4-aligned
            float4 v = ((unsigned)xq < (unsigned)IMG_W)
                           ? *reinterpret_cast<const float4*>(row + xq)
                           : INF4;
            f[q * 4 + 0] = v.x;
            f[q * 4 + 1] = v.y;
            f[q * 4 + 2] = v.z;
            f[q * 4 + 3] = v.w;
        }

        float core = f[4];
#pragma unroll
        for (int k = 5; k <= 15; ++k) core = fminf(core, f[k]);

        float p23   = fminf(f[2], f[3]);
        float p1617 = fminf(f[16], f[17]);

        float4 o;
        o.x = fminf(core, fminf(f[1], p23));
        o.y = fminf(core, fminf(p23, f[16]));
        o.z = fminf(core, fminf(f[3], p1617));
        o.w = fminf(core, fminf(p1617, f[18]));

        *reinterpret_cast<float4*>(ob + (size_t)r * IMG_W) = o;
    }
}

extern "C" void kernel_launch(void* const* d_in, const int* in_sizes, int n_in,
                              void* d_out, int out_size) {
    const float* img = (const float*)d_in[0];
    float* out = (float*)d_out;

    const int smem = YTILE * IMG_W * sizeof(float);   // 61440 B
    static bool attr_set = false;
    if (!attr_set) {
        cudaFuncSetAttribute(k_fused, cudaFuncAttributeMaxDynamicSharedMemorySize, smem);
        attr_set = true;
    }

    dim3 grid((IMG_H + YTILE - 1) / YTILE, IMG_B);    // 69 x 16
    k_fused<<<grid, 512, smem>>>(img, out);
}